// round 1
// baseline (speedup 1.0000x reference)
#include <cuda_runtime.h>

#define INN   50000
#define NB    8
#define INC   32
#define NINC  256     // NB*INC
#define OUTN  8192
#define OUTC  32
#define MAXD  16
#define O_TILE 16

// Scratch: transposed embedding table xT[i][n*INC+c] = x[n][c][i]  (51.2 MB)
__device__ float g_xT[INN * NINC];

// ---------------------------------------------------------------------------
// Kernel 1: transpose x [256][50000] -> xT [50000][256]
// Standard 32x32 shared-memory tile, padded to kill bank conflicts.
// ---------------------------------------------------------------------------
__global__ __launch_bounds__(256) void fgl_transpose_kernel(const float* __restrict__ x) {
    __shared__ float tile[32][33];
    const int i0 = blockIdx.x * 32;   // inn tile base
    const int r0 = blockIdx.y * 32;   // (n*INC+c) tile base
    const int tx = threadIdx.x;       // 0..31
    const int ty = threadIdx.y;       // 0..7

    #pragma unroll
    for (int k = 0; k < 32; k += 8) {
        int i = i0 + tx;
        int r = r0 + ty + k;
        if (i < INN) tile[ty + k][tx] = x[r * INN + i];
    }
    __syncthreads();
    #pragma unroll
    for (int k = 0; k < 32; k += 8) {
        int i = i0 + ty + k;
        int r = r0 + tx;
        if (i < INN) g_xT[i * NINC + r] = tile[tx][ty + k];
    }
}

// ---------------------------------------------------------------------------
// Kernel 2: gather + masked pool + shared-weight GEMM + bias, fused.
// One CTA handles O_TILE=16 output nodes. 256 threads.
//   Phase A: pooled[o][t] = sum_d mask[o,d] * xT[A[o,d]][t]   (coalesced 1KB rows)
//   Phase B: per-thread 16-wide register GEMM: out[n,dc,o] = bias + pooled @ W
// ---------------------------------------------------------------------------
__global__ __launch_bounds__(256) void fgl_gather_mm_kernel(
    const int*   __restrict__ A,
    const float* __restrict__ mask,
    const float* __restrict__ weight,   // [INC][OUTC]
    const float* __restrict__ bias,     // [OUTC][OUTN]
    float*       __restrict__ out)      // [NB][OUTC][OUTN]
{
    __shared__ int   sidx[O_TILE * MAXD];
    __shared__ float smsk[O_TILE * MAXD];
    __shared__ float pooled[O_TILE][NINC + 1];   // stride 257 -> conflict-free
    __shared__ float wsh[INC * OUTC];

    const int t     = threadIdx.x;
    const int obase = blockIdx.x * O_TILE;

    // Load adjacency + mask for this tile (256 each)
    sidx[t] = A[obase * MAXD + t];
    smsk[t] = mask[obase * MAXD + t];
    // Load weight (1024 floats)
    #pragma unroll
    for (int k = t; k < INC * OUTC; k += 256) wsh[k] = weight[k];
    __syncthreads();

    // ---- Phase A: gather + masked pool ----
    // Each o-iteration issues 16 independent coalesced loads (MLP >= 16).
    #pragma unroll 2
    for (int o = 0; o < O_TILE; ++o) {
        float acc = 0.f;
        #pragma unroll
        for (int d = 0; d < MAXD; ++d) {
            int   idx = sidx[o * MAXD + d];
            float m   = smsk[o * MAXD + d];
            acc += m * __ldg(&g_xT[idx * NINC + t]);
        }
        pooled[o][t] = acc;
    }
    __syncthreads();

    // ---- Phase B: micro-GEMM + bias ----
    // Thread mapping: oo = t&15, h = t>>4; n = h>>1 (0..7), dch half = (h&1)*16.
    // Within a warp all lanes share n; pooled reads are conflict-free
    // (stride-257 rows, lanes 16..31 broadcast-duplicate lanes 0..15).
    const int oo = t & 15;
    const int h  = t >> 4;
    const int n  = h >> 1;
    const int dh = (h & 1) * 16;

    float acc[16];
    #pragma unroll
    for (int j = 0; j < 16; ++j)
        acc[j] = bias[(dh + j) * OUTN + obase + oo];

    #pragma unroll
    for (int c = 0; c < INC; ++c) {
        float p = pooled[oo][n * INC + c];
        #pragma unroll
        for (int j = 0; j < 16; ++j)
            acc[j] += p * wsh[c * OUTC + dh + j];
    }

    #pragma unroll
    for (int j = 0; j < 16; ++j)
        out[(n * OUTC + dh + j) * OUTN + obase + oo] = acc[j];
}

// ---------------------------------------------------------------------------
// Inputs (metadata order): x [8,32,50000] f32, A [8192,16] i32,
// mask [8192,16,1] f32, weight [32,32] f32, bias [32,8192] f32.
// Output: y [8,32,8192] f32.
// ---------------------------------------------------------------------------
extern "C" void kernel_launch(void* const* d_in, const int* in_sizes, int n_in,
                              void* d_out, int out_size) {
    const float* x      = (const float*)d_in[0];
    const int*   A      = (const int*)  d_in[1];
    const float* mask   = (const float*)d_in[2];
    const float* weight = (const float*)d_in[3];
    const float* bias   = (const float*)d_in[4];
    float*       out    = (float*)d_out;

    dim3 tb(32, 8);
    dim3 tg((INN + 31) / 32, NINC / 32);
    fgl_transpose_kernel<<<tg, tb>>>(x);

    fgl_gather_mm_kernel<<<OUTN / O_TILE, 256>>>(A, mask, weight, bias, out);
}

// round 2
// speedup vs baseline: 1.0467x; 1.0467x over previous
#include <cuda_runtime.h>

#define INN   50000
#define NB    8
#define INC   32
#define NINC  256     // NB*INC floats per table row
#define NINC4 64      // float4 per table row
#define OUTN  8192
#define OUTC  32
#define MAXD  16
#define O_TILE 8
#define P_STRIDE 260  // pooled row stride (floats): 16B-aligned, conflict-free

// Scratch: transposed embedding table xT[i][n*INC+c] = x[n][c][i]  (51.2 MB)
__device__ float g_xT[INN * NINC];

// ---------------------------------------------------------------------------
// Kernel 1: transpose x [256][50000] -> xT [50000][256]
// ---------------------------------------------------------------------------
__global__ __launch_bounds__(256) void fgl_transpose_kernel(const float* __restrict__ x) {
    __shared__ float tile[32][33];
    const int i0 = blockIdx.x * 32;   // inn tile base
    const int r0 = blockIdx.y * 32;   // (n*INC+c) tile base
    const int tx = threadIdx.x;       // 0..31
    const int ty = threadIdx.y;       // 0..7

    #pragma unroll
    for (int k = 0; k < 32; k += 8) {
        int i = i0 + tx;
        int r = r0 + ty + k;
        if (i < INN) tile[ty + k][tx] = x[r * INN + i];
    }
    __syncthreads();
    #pragma unroll
    for (int k = 0; k < 32; k += 8) {
        int i = i0 + ty + k;
        int r = r0 + tx;
        if (i < INN) g_xT[i * NINC + r] = tile[tx][ty + k];
    }
}

// ---------------------------------------------------------------------------
// Kernel 2: gather + masked pool + shared-weight GEMM + bias, fused.
// One CTA handles O_TILE=8 output nodes, 256 threads, 1024 CTAs.
//
// Phase A: thread t -> ol = t>>6 (0..3), cg = t&63 (float4 column group).
//          For o in {ol, ol+4}: acc4 = sum_d mask * xT4[A[o,d]*64 + cg]
//          Warp = 32 consecutive cg, same o -> 512B contiguous per LDG.128.
// Phase B: thread t -> oo = t&7, h = t>>3; n = h>>2 (0..7), dh = (h&3)*8.
//          8-accumulator register GEMM over c=0..31.
// ---------------------------------------------------------------------------
__global__ __launch_bounds__(256) void fgl_gather_mm_kernel(
    const int*   __restrict__ A,
    const float* __restrict__ mask,
    const float* __restrict__ weight,   // [INC][OUTC]
    const float* __restrict__ bias,     // [OUTC][OUTN]
    float*       __restrict__ out)      // [NB][OUTC][OUTN]
{
    __shared__ int   sidx[O_TILE * MAXD];            // 128
    __shared__ float smsk[O_TILE * MAXD];            // 128
    __shared__ float pooled[O_TILE][P_STRIDE];       // 8 x 260
    __shared__ float wsh[INC * OUTC];                // 1024

    const int t     = threadIdx.x;
    const int obase = blockIdx.x * O_TILE;

    // Load adjacency + mask (128 each) and weight (1024)
    if (t < O_TILE * MAXD) {
        sidx[t] = A[obase * MAXD + t];
        smsk[t] = mask[obase * MAXD + t];
    }
    #pragma unroll
    for (int k = t; k < INC * OUTC; k += 256) wsh[k] = weight[k];
    __syncthreads();

    // ---- Phase A: vectorized gather + masked pool ----
    const float4* __restrict__ xT4 = (const float4*)g_xT;
    const int ol = t >> 6;     // 0..3
    const int cg = t & 63;     // float4 column group

    #pragma unroll
    for (int oi = 0; oi < 2; ++oi) {
        const int o = ol + oi * 4;
        float4 acc = make_float4(0.f, 0.f, 0.f, 0.f);
        #pragma unroll
        for (int d = 0; d < MAXD; ++d) {
            const int   idx = sidx[o * MAXD + d];
            const float m   = smsk[o * MAXD + d];
            float4 v = __ldg(&xT4[idx * NINC4 + cg]);
            acc.x += m * v.x;
            acc.y += m * v.y;
            acc.z += m * v.z;
            acc.w += m * v.w;
        }
        *(float4*)&pooled[o][4 * cg] = acc;
    }
    __syncthreads();

    // ---- Phase B: micro-GEMM + bias ----
    const int oo = t & 7;           // output-node within tile
    const int h  = t >> 3;          // 0..31
    const int n  = h >> 2;          // batch 0..7
    const int dh = (h & 3) * 8;     // outc half-group base

    float acc[8];
    #pragma unroll
    for (int j = 0; j < 8; ++j)
        acc[j] = bias[(dh + j) * OUTN + obase + oo];

    #pragma unroll
    for (int c = 0; c < INC; ++c) {
        const float p = pooled[oo][n * INC + c];
        #pragma unroll
        for (int j = 0; j < 8; ++j)
            acc[j] += p * wsh[c * OUTC + dh + j];
    }

    #pragma unroll
    for (int j = 0; j < 8; ++j)
        out[(n * OUTC + dh + j) * OUTN + obase + oo] = acc[j];
}

// ---------------------------------------------------------------------------
// Inputs (metadata order): x [8,32,50000] f32, A [8192,16] i32,
// mask [8192,16,1] f32, weight [32,32] f32, bias [32,8192] f32.
// Output: y [8,32,8192] f32.
// ---------------------------------------------------------------------------
extern "C" void kernel_launch(void* const* d_in, const int* in_sizes, int n_in,
                              void* d_out, int out_size) {
    const float* x      = (const float*)d_in[0];
    const int*   A      = (const int*)  d_in[1];
    const float* mask   = (const float*)d_in[2];
    const float* weight = (const float*)d_in[3];
    const float* bias   = (const float*)d_in[4];
    float*       out    = (float*)d_out;

    dim3 tb(32, 8);
    dim3 tg((INN + 31) / 32, NINC / 32);
    fgl_transpose_kernel<<<tg, tb>>>(x);

    fgl_gather_mm_kernel<<<OUTN / O_TILE, 256>>>(A, mask, weight, bias, out);
}